// round 4
// baseline (speedup 1.0000x reference)
#include <cuda_runtime.h>
#include <math.h>

#define NN 50000
#define NE 600000
#define NG 128
#define CDIM 128
#define M3 384
#define CAT 1152
#define EPSB 1e-5f

// ---------------- static scratch (no allocations allowed) ----------------
__device__ float d_neigh[(size_t)NN * CDIM];
__device__ float d_X[(size_t)NN * CDIM];
__device__ float d_H1[(size_t)NN * CDIM];
__device__ float d_H2[(size_t)NN * CDIM];
__device__ float d_Hm[(size_t)NN * M3];
__device__ float d_stX[2 * CDIM];
__device__ float d_stH[2 * M3];
__device__ float d_scX[CDIM];
__device__ float d_shX[CDIM];
__device__ float d_Hcat[NG * CAT];
__device__ float d_Hbn[NG * CAT];
__device__ float d_h1[NG * 768];
__device__ float d_h2[NG * 384];

// ---------------- tf32 helpers ----------------
__device__ __forceinline__ unsigned f2tf32(float v) {
    unsigned r;
    asm("cvt.rna.tf32.f32 %0, %1;" : "=r"(r) : "f"(v));
    return r;
}
__device__ __forceinline__ void mma_tf32(float* c, const unsigned* a, const unsigned* b) {
    asm volatile(
        "mma.sync.aligned.m16n8k8.row.col.f32.tf32.tf32.f32 "
        "{%0,%1,%2,%3}, {%4,%5,%6,%7}, {%8,%9}, {%0,%1,%2,%3};"
        : "+f"(c[0]), "+f"(c[1]), "+f"(c[2]), "+f"(c[3])
        : "r"(a[0]), "r"(a[1]), "r"(a[2]), "r"(a[3]), "r"(b[0]), "r"(b[1]));
}

// ---------------- zero scratch used by atomics / stats ----------------
__global__ void zero_all_k() {
    size_t i = (size_t)blockIdx.x * blockDim.x + threadIdx.x;
    d_neigh[i] = 0.f;
    d_H1[i] = 0.f;
    d_H2[i] = 0.f;
    if (i < 2 * CDIM) d_stX[i] = 0.f;
    if (i < 2 * M3) d_stH[i] = 0.f;
}

// ---------------- edge scatter: dst[sidx[e]] += src[gidx[e]] ----------------
// one warp per edge; optional per-channel affine (sc/sh) applied to gathered value
__global__ void scatter_add_k(const float* __restrict__ src, float* __restrict__ dst,
                              const int* __restrict__ gidx, const int* __restrict__ sidx,
                              const float* __restrict__ sc, const float* __restrict__ sh) {
    long t = (long)blockIdx.x * blockDim.x + threadIdx.x;
    int e = (int)(t >> 5);
    if (e >= NE) return;
    int q = (int)(t & 31);
    int g = __ldg(gidx + e);
    int s = __ldg(sidx + e);
    float4 v = __ldg((const float4*)src + (size_t)g * 32 + q);
    if (sc) {
        float4 s4 = __ldg((const float4*)sc + q);
        float4 h4 = __ldg((const float4*)sh + q);
        v.x = fmaf(v.x, s4.x, h4.x);
        v.y = fmaf(v.y, s4.y, h4.y);
        v.z = fmaf(v.z, s4.z, h4.z);
        v.w = fmaf(v.w, s4.w, h4.w);
    }
    float4* p = (float4*)dst + (size_t)s * 32 + q;
    asm volatile("red.global.add.v4.f32 [%0], {%1,%2,%3,%4};"
                 :: "l"(p), "f"(v.x), "f"(v.y), "f"(v.z), "f"(v.w)
                 : "memory");
}

// ================= tf32 tensor-core GEMM core =================
// Block tile 128(M) x 128(N), K=128 per input, up to 3 (A_i, W_i) pairs summed.
// 256 threads = 8 warps (4 row x 2 col); warp tile 32x64.
// Optional per-input channel affine on A (BN fusion). Epilogue writes C+bias and
// accumulates per-column sum/sumsq into global stats via smem reduction.
__device__ __forceinline__ void gemm_core(
    const float* const* Ap, const float* const* Wp,
    const float* const* scp, const float* const* shp, int nIn, int ldw,
    const float* __restrict__ bias, float* __restrict__ Cp, int ldc,
    int r0, int cbase, float* __restrict__ st_sum, float* __restrict__ st_sq,
    unsigned (*As)[36], unsigned (*Ws)[36], float* s_red) {
    const int tx = threadIdx.x;
    const int lane = tx & 31;
    const int warp = tx >> 5;
    const int wr = (warp & 3) * 32;
    const int wc = (warp >> 2) * 64;
    const int g = lane >> 2;
    const int t4 = lane & 3;

    float acc[2][8][4];
#pragma unroll
    for (int mi = 0; mi < 2; mi++)
#pragma unroll
        for (int ni = 0; ni < 8; ni++)
#pragma unroll
            for (int j = 0; j < 4; j++) acc[mi][ni][j] = 0.f;

    for (int i = 0; i < nIn; ++i) {
        const float* A = Ap[i];
        const float* W = Wp[i];
        const float* sc = scp[i];
        const float* sh = shp[i];
        for (int kb = 0; kb < 128; kb += 32) {
            __syncthreads();
#pragma unroll
            for (int it = 0; it < 4; ++it) {
                int s = tx + it * 256;     // 0..1023
                int rr = s >> 3;           // 0..127
                int kq = (s & 7) * 4;      // 0..28
                float4 va = make_float4(0.f, 0.f, 0.f, 0.f);
                if (r0 + rr < NN)
                    va = __ldg((const float4*)(A + (size_t)(r0 + rr) * CDIM + kb + kq));
                if (sc) {
                    float4 s4 = __ldg((const float4*)(sc + kb + kq));
                    float4 h4 = __ldg((const float4*)(sh + kb + kq));
                    va.x = fmaf(va.x, s4.x, h4.x);
                    va.y = fmaf(va.y, s4.y, h4.y);
                    va.z = fmaf(va.z, s4.z, h4.z);
                    va.w = fmaf(va.w, s4.w, h4.w);
                }
                As[rr][kq + 0] = f2tf32(va.x); As[rr][kq + 1] = f2tf32(va.y);
                As[rr][kq + 2] = f2tf32(va.z); As[rr][kq + 3] = f2tf32(va.w);
                float4 vw = __ldg((const float4*)(W + (size_t)rr * ldw + kb + kq));
                Ws[rr][kq + 0] = f2tf32(vw.x); Ws[rr][kq + 1] = f2tf32(vw.y);
                Ws[rr][kq + 2] = f2tf32(vw.z); Ws[rr][kq + 3] = f2tf32(vw.w);
            }
            __syncthreads();
#pragma unroll
            for (int kk = 0; kk < 32; kk += 8) {
                unsigned a[2][4], b[8][2];
#pragma unroll
                for (int mi = 0; mi < 2; mi++) {
                    int r = wr + mi * 16;
                    a[mi][0] = As[r + g][kk + t4];
                    a[mi][1] = As[r + g + 8][kk + t4];
                    a[mi][2] = As[r + g][kk + t4 + 4];
                    a[mi][3] = As[r + g + 8][kk + t4 + 4];
                }
#pragma unroll
                for (int ni = 0; ni < 8; ni++) {
                    int n = wc + ni * 8 + g;
                    b[ni][0] = Ws[n][kk + t4];
                    b[ni][1] = Ws[n][kk + t4 + 4];
                }
#pragma unroll
                for (int mi = 0; mi < 2; mi++)
#pragma unroll
                    for (int ni = 0; ni < 8; ni++)
                        mma_tf32(acc[mi][ni], a[mi], b[ni]);
            }
        }
    }

    // epilogue: bias, write C, per-column stats
    s_red[tx] = 0.f;  // 256 slots: [0:128)=sum, [128:256)=sumsq
    __syncthreads();
#pragma unroll
    for (int mi = 0; mi < 2; mi++) {
        int r1 = r0 + wr + mi * 16 + g;
        int r2 = r1 + 8;
#pragma unroll
        for (int ni = 0; ni < 8; ni++) {
            int cc = wc + ni * 8 + 2 * t4;
            float b0 = bias[cc], b1 = bias[cc + 1];
            float v0 = acc[mi][ni][0] + b0, v1 = acc[mi][ni][1] + b1;
            float v2 = acc[mi][ni][2] + b0, v3 = acc[mi][ni][3] + b1;
            float a0 = 0.f, a1 = 0.f, q0 = 0.f, q1 = 0.f;
            if (r1 < NN) {
                Cp[(size_t)r1 * ldc + cbase + cc] = v0;
                Cp[(size_t)r1 * ldc + cbase + cc + 1] = v1;
                a0 += v0; q0 += v0 * v0; a1 += v1; q1 += v1 * v1;
            }
            if (r2 < NN) {
                Cp[(size_t)r2 * ldc + cbase + cc] = v2;
                Cp[(size_t)r2 * ldc + cbase + cc + 1] = v3;
                a0 += v2; q0 += v2 * v2; a1 += v3; q1 += v3 * v3;
            }
            atomicAdd(&s_red[cc], a0);
            atomicAdd(&s_red[cc + 1], a1);
            atomicAdd(&s_red[128 + cc], q0);
            atomicAdd(&s_red[128 + cc + 1], q1);
        }
    }
    __syncthreads();
    if (tx < 128) {
        atomicAdd(st_sum + tx, s_red[tx]);
        atomicAdd(st_sq + tx, s_red[128 + tx]);
    }
}

// X = neigh @ w_rel^T + x @ w_root^T + b_rel  (+ column stats into d_stX)
__global__ void __launch_bounds__(256, 1) gemm_x_k(
    const float* __restrict__ A0, const float* __restrict__ A1,
    const float* __restrict__ W0, const float* __restrict__ W1,
    const float* __restrict__ bias, float* __restrict__ Cp) {
    __shared__ unsigned As[128][36];
    __shared__ unsigned Ws[128][36];
    __shared__ float s_red[256];
    const float* Ap[3] = {A0, A1, nullptr};
    const float* Wp[3] = {W0, W1, nullptr};
    const float* Zn[3] = {nullptr, nullptr, nullptr};
    gemm_core(Ap, Wp, Zn, Zn, 2, 128, bias, Cp, 128, blockIdx.x * 128, 0,
              d_stX, d_stX + CDIM, As, Ws, s_red);
}

// Hm strips: strip j uses inputs [BN(X),H1,H2][0..j], W block row j (+ stats into d_stH)
__global__ void __launch_bounds__(256, 1) gemm_hm_k(
    const float* __restrict__ lin_w, const float* __restrict__ lin_b) {
    __shared__ unsigned As[128][36];
    __shared__ unsigned Ws[128][36];
    __shared__ float s_red[256];
    int j = blockIdx.y;
    const float* Ap[3] = {d_X, d_H1, d_H2};
    const float* Wp[3];
    for (int i = 0; i < 3; i++)
        Wp[i] = lin_w + (size_t)(j * 128) * M3 + i * 128;
    const float* Sc[3] = {d_scX, nullptr, nullptr};
    const float* Sh[3] = {d_shX, nullptr, nullptr};
    gemm_core(Ap, Wp, Sc, Sh, j + 1, M3, lin_b + j * 128, d_Hm, M3,
              blockIdx.x * 128, j * 128,
              d_stH + j * 128, d_stH + M3 + j * 128, As, Ws, s_red);
}

// ---------------- finalize BN(X): stats -> per-channel scale/shift ----------------
__global__ void finalize_bnX_k(const float* __restrict__ gw, const float* __restrict__ gb) {
    int c = threadIdx.x;  // 128
    float mean = d_stX[c] * (1.f / NN);
    float var = d_stX[CDIM + c] * (1.f / NN) - mean * mean;
    float sc = gw[c] * rsqrtf(var + EPSB);
    d_scX[c] = sc;
    d_shX[c] = gb[c] - mean * sc;
}

// ---------------- pooling (fuses bnh BatchNorm apply) ----------------
__global__ void pool_k(const int* __restrict__ batch,
                       const float* __restrict__ gw, const float* __restrict__ gb) {
    int g = blockIdx.x;
    int c = threadIdx.x;  // 384
    int lo = 0, hi = NN;
    while (lo < hi) { int mid = (lo + hi) >> 1; if (batch[mid] < g) lo = mid + 1; else hi = mid; }
    int start = lo;
    lo = start; hi = NN;
    while (lo < hi) { int mid = (lo + hi) >> 1; if (batch[mid] < g + 1) lo = mid + 1; else hi = mid; }
    int end = lo;

    float mean = d_stH[c] * (1.f / NN);
    float var = d_stH[M3 + c] * (1.f / NN) - mean * mean;
    float sc = gw[c] * rsqrtf(var + EPSB);
    float sh = gb[c] - mean * sc;

    float s = 0.f;
    float mx = -INFINITY;
    for (int r = start; r < end; ++r) {
        float v = fmaf(d_Hm[(size_t)r * M3 + c], sc, sh);
        s += v;
        mx = fmaxf(mx, v);
    }
    int cnt = end - start;
    d_Hcat[(size_t)g * CAT + c] = (cnt > 0) ? s / (float)cnt : 0.f;
    d_Hcat[(size_t)g * CAT + 384 + c] = s;
    d_Hcat[(size_t)g * CAT + 768 + c] = (cnt > 0) ? mx : 0.f;
}

// ---------------- BN over graphs (128 rows x 1152 cols) ----------------
__global__ void bn_graphs_k(const float* __restrict__ gw, const float* __restrict__ gb) {
    int c = blockIdx.x * blockDim.x + threadIdx.x;
    if (c >= CAT) return;
    float s = 0.f, ss = 0.f;
    for (int r = 0; r < NG; r++) { float v = d_Hcat[r * CAT + c]; s += v; ss += v * v; }
    float mean = s * (1.f / NG);
    float var = ss * (1.f / NG) - mean * mean;
    float sc = gw[c] * rsqrtf(var + EPSB);
    float sh = gb[c] - mean * sc;
    for (int r = 0; r < NG; r++) d_Hbn[r * CAT + c] = fmaf(d_Hcat[r * CAT + c], sc, sh);
}

// ---------------- small dense layer ----------------
__global__ void mlp_k(const float* __restrict__ A, int Kd,
                      const float* __restrict__ W, const float* __restrict__ bias,
                      float* __restrict__ out, int Od, int do_relu) {
    extern __shared__ float sA[];  // 8*Kd
    int g0 = blockIdx.y * 8;
    for (int idx = threadIdx.x; idx < 8 * Kd; idx += blockDim.x)
        sA[idx] = A[(size_t)(g0 + idx / Kd) * Kd + (idx % Kd)];
    __syncthreads();
    int o = blockIdx.x * blockDim.x + threadIdx.x;
    float bb = bias[o];
    float acc[8];
#pragma unroll
    for (int j = 0; j < 8; j++) acc[j] = bb;
    const float* wr = W + (size_t)o * Kd;
    for (int k = 0; k < Kd; k++) {
        float w = wr[k];
#pragma unroll
        for (int j = 0; j < 8; j++) acc[j] = fmaf(w, sA[j * Kd + k], acc[j]);
    }
#pragma unroll
    for (int j = 0; j < 8; j++) {
        float v = acc[j];
        if (do_relu) v = fmaxf(v, 0.f);
        out[(size_t)(g0 + j) * Od + o] = v;
    }
}

// ---------------- final layer + log_softmax ----------------
__global__ void final_k(const float* __restrict__ w3, const float* __restrict__ b3,
                        float* __restrict__ out) {
    int g = threadIdx.x;
    if (g >= NG) return;
    float l0 = b3[0], l1 = b3[1];
    const float* h = d_h2 + (size_t)g * 384;
    for (int k = 0; k < 384; k++) {
        float v = h[k];
        l0 = fmaf(v, w3[k], l0);
        l1 = fmaf(v, w3[384 + k], l1);
    }
    float m = fmaxf(l0, l1);
    float lse = m + logf(expf(l0 - m) + expf(l1 - m));
    out[g * 2 + 0] = l0 - lse;
    out[g * 2 + 1] = l1 - lse;
}

extern "C" void kernel_launch(void* const* d_in, const int* in_sizes, int n_in,
                              void* d_out, int out_size) {
    const float* x      = (const float*)d_in[0];
    const int*   ei     = (const int*)d_in[1];
    const int*   batch  = (const int*)d_in[2];
    const float* w_rel  = (const float*)d_in[4];
    const float* b_rel  = (const float*)d_in[5];
    const float* w_root = (const float*)d_in[6];
    const float* n0g    = (const float*)d_in[7];
    const float* n0b    = (const float*)d_in[8];
    const float* lin_w  = (const float*)d_in[9];
    const float* lin_b  = (const float*)d_in[10];
    const float* bnh_g  = (const float*)d_in[11];
    const float* bnh_b  = (const float*)d_in[12];
    const float* bno_g  = (const float*)d_in[13];
    const float* bno_b  = (const float*)d_in[14];
    const float* w1     = (const float*)d_in[15];
    const float* b1     = (const float*)d_in[16];
    const float* w2     = (const float*)d_in[17];
    const float* b2     = (const float*)d_in[18];
    const float* w3     = (const float*)d_in[19];
    const float* b3     = (const float*)d_in[20];
    float* out = (float*)d_out;
    const int* row = ei;            // edge_index[0]
    const int* col = ei + NE;       // edge_index[1]

    float *p_neigh, *p_X, *p_H1, *p_H2, *p_scX, *p_shX, *p_Hbn, *p_h1, *p_h2;
    cudaGetSymbolAddress((void**)&p_neigh, d_neigh);
    cudaGetSymbolAddress((void**)&p_X, d_X);
    cudaGetSymbolAddress((void**)&p_H1, d_H1);
    cudaGetSymbolAddress((void**)&p_H2, d_H2);
    cudaGetSymbolAddress((void**)&p_scX, d_scX);
    cudaGetSymbolAddress((void**)&p_shX, d_shX);
    cudaGetSymbolAddress((void**)&p_Hbn, d_Hbn);
    cudaGetSymbolAddress((void**)&p_h1, d_h1);
    cudaGetSymbolAddress((void**)&p_h2, d_h2);

    const int ROWBLK = (NN + 127) / 128;  // 391

    zero_all_k<<<(NN * CDIM) / 256, 256>>>();
    // neigh[col] += x[row]
    scatter_add_k<<<(NE * 32) / 256, 256>>>(x, p_neigh, row, col, nullptr, nullptr);
    // X = neigh @ w_rel^T + x @ w_root^T + b_rel   (stats folded into epilogue)
    gemm_x_k<<<ROWBLK, 256>>>(p_neigh, x, w_rel, w_root, b_rel, p_X);
    finalize_bnX_k<<<1, 128>>>(n0g, n0b);
    // H1[row] += BN(X)[col]  (affine fused into gather), H2[row] += H1[col]
    scatter_add_k<<<(NE * 32) / 256, 256>>>(p_X, p_H1, col, row, p_scX, p_shX);
    scatter_add_k<<<(NE * 32) / 256, 256>>>(p_H1, p_H2, col, row, nullptr, nullptr);
    // masked block-lower-triangular lin GEMM, 3 strips, BN(X) fused on input 0,
    // bnh stats folded into epilogue
    gemm_hm_k<<<dim3(ROWBLK, 3), 256>>>(lin_w, lin_b);
    pool_k<<<NG, 384>>>(batch, bnh_g, bnh_b);
    bn_graphs_k<<<CAT / 128, 128>>>(bno_g, bno_b);
    mlp_k<<<dim3(768 / 128, NG / 8), 128, 8 * 1152 * sizeof(float)>>>(
        p_Hbn, 1152, w1, b1, p_h1, 768, 1);
    mlp_k<<<dim3(384 / 128, NG / 8), 128, 8 * 768 * sizeof(float)>>>(
        p_h1, 768, w2, b2, p_h2, 384, 1);
    final_k<<<1, 128>>>(w3, b3, out);
}

// round 5
// speedup vs baseline: 1.3603x; 1.3603x over previous
#include <cuda_runtime.h>
#include <math.h>

#define NN 50000
#define NE 600000
#define NG 128
#define CDIM 128
#define M3 384
#define CAT 1152
#define EPSB 1e-5f

// ---------------- static scratch (no allocations allowed) ----------------
__device__ float d_neigh[(size_t)NN * CDIM];
__device__ float d_X[(size_t)NN * CDIM];
__device__ float d_H1[(size_t)NN * CDIM];
__device__ float d_H2[(size_t)NN * CDIM];
__device__ float d_Hm[(size_t)NN * M3];
__device__ float d_stX[2 * CDIM];
__device__ float d_stH[2 * M3];
__device__ float d_scX[CDIM];
__device__ float d_shX[CDIM];
__device__ float d_Hcat[NG * CAT];
__device__ float d_Hbn[NG * CAT];
__device__ float d_h1[NG * 768];
__device__ float d_h2[NG * 384];

// ---------------- tf32 helpers ----------------
__device__ __forceinline__ unsigned f2tf32(float v) {
    unsigned r;
    asm("cvt.rna.tf32.f32 %0, %1;" : "=r"(r) : "f"(v));
    return r;
}
__device__ __forceinline__ void mma_tf32(float* c, const unsigned* a, const unsigned* b) {
    asm volatile(
        "mma.sync.aligned.m16n8k8.row.col.f32.tf32.tf32.f32 "
        "{%0,%1,%2,%3}, {%4,%5,%6,%7}, {%8,%9}, {%0,%1,%2,%3};"
        : "+f"(c[0]), "+f"(c[1]), "+f"(c[2]), "+f"(c[3])
        : "r"(a[0]), "r"(a[1]), "r"(a[2]), "r"(a[3]), "r"(b[0]), "r"(b[1]));
}

// ---------------- zero scratch used by atomics / stats ----------------
__global__ void zero_all_k() {
    size_t i = (size_t)blockIdx.x * blockDim.x + threadIdx.x;
    d_neigh[i] = 0.f;
    d_H1[i] = 0.f;
    d_H2[i] = 0.f;
    if (i < 2 * CDIM) d_stX[i] = 0.f;
    if (i < 2 * M3) d_stH[i] = 0.f;
}

// ---------------- edge scatter: dst[sidx[e]] += src[gidx[e]] ----------------
// one warp per edge; optional per-channel affine (sc/sh) applied to gathered value
__global__ void scatter_add_k(const float* __restrict__ src, float* __restrict__ dst,
                              const int* __restrict__ gidx, const int* __restrict__ sidx,
                              const float* __restrict__ sc, const float* __restrict__ sh) {
    long t = (long)blockIdx.x * blockDim.x + threadIdx.x;
    int e = (int)(t >> 5);
    if (e >= NE) return;
    int q = (int)(t & 31);
    int g = __ldg(gidx + e);
    int s = __ldg(sidx + e);
    float4 v = __ldg((const float4*)src + (size_t)g * 32 + q);
    if (sc) {
        float4 s4 = __ldg((const float4*)sc + q);
        float4 h4 = __ldg((const float4*)sh + q);
        v.x = fmaf(v.x, s4.x, h4.x);
        v.y = fmaf(v.y, s4.y, h4.y);
        v.z = fmaf(v.z, s4.z, h4.z);
        v.w = fmaf(v.w, s4.w, h4.w);
    }
    float4* p = (float4*)dst + (size_t)s * 32 + q;
    asm volatile("red.global.add.v4.f32 [%0], {%1,%2,%3,%4};"
                 :: "l"(p), "f"(v.x), "f"(v.y), "f"(v.z), "f"(v.w)
                 : "memory");
}

// ================= tf32 tensor-core GEMM core (R2 version, no stats) =================
// Block tile 128(M) x 128(N), K=128 per input, up to 3 (A_i, W_i) pairs summed.
// 256 threads = 8 warps (4 row x 2 col); warp tile 32x64.
// Optional per-input channel affine on A (BN fusion).
__device__ __forceinline__ void gemm_core(
    const float* const* Ap, const float* const* Wp,
    const float* const* scp, const float* const* shp, int nIn, int ldw,
    const float* __restrict__ bias, float* __restrict__ Cp, int ldc,
    int r0, int cbase, unsigned (*As)[36], unsigned (*Ws)[36]) {
    const int tx = threadIdx.x;
    const int lane = tx & 31;
    const int warp = tx >> 5;
    const int wr = (warp & 3) * 32;
    const int wc = (warp >> 2) * 64;
    const int g = lane >> 2;
    const int t4 = lane & 3;

    float acc[2][8][4];
#pragma unroll
    for (int mi = 0; mi < 2; mi++)
#pragma unroll
        for (int ni = 0; ni < 8; ni++)
#pragma unroll
            for (int j = 0; j < 4; j++) acc[mi][ni][j] = 0.f;

    for (int i = 0; i < nIn; ++i) {
        const float* A = Ap[i];
        const float* W = Wp[i];
        const float* sc = scp[i];
        const float* sh = shp[i];
        for (int kb = 0; kb < 128; kb += 32) {
            __syncthreads();
#pragma unroll
            for (int it = 0; it < 4; ++it) {
                int s = tx + it * 256;     // 0..1023
                int rr = s >> 3;           // 0..127
                int kq = (s & 7) * 4;      // 0..28
                float4 va = make_float4(0.f, 0.f, 0.f, 0.f);
                if (r0 + rr < NN)
                    va = __ldg((const float4*)(A + (size_t)(r0 + rr) * CDIM + kb + kq));
                if (sc) {
                    float4 s4 = __ldg((const float4*)(sc + kb + kq));
                    float4 h4 = __ldg((const float4*)(sh + kb + kq));
                    va.x = fmaf(va.x, s4.x, h4.x);
                    va.y = fmaf(va.y, s4.y, h4.y);
                    va.z = fmaf(va.z, s4.z, h4.z);
                    va.w = fmaf(va.w, s4.w, h4.w);
                }
                As[rr][kq + 0] = f2tf32(va.x); As[rr][kq + 1] = f2tf32(va.y);
                As[rr][kq + 2] = f2tf32(va.z); As[rr][kq + 3] = f2tf32(va.w);
                float4 vw = __ldg((const float4*)(W + (size_t)rr * ldw + kb + kq));
                Ws[rr][kq + 0] = f2tf32(vw.x); Ws[rr][kq + 1] = f2tf32(vw.y);
                Ws[rr][kq + 2] = f2tf32(vw.z); Ws[rr][kq + 3] = f2tf32(vw.w);
            }
            __syncthreads();
#pragma unroll
            for (int kk = 0; kk < 32; kk += 8) {
                unsigned a[2][4], b[8][2];
#pragma unroll
                for (int mi = 0; mi < 2; mi++) {
                    int r = wr + mi * 16;
                    a[mi][0] = As[r + g][kk + t4];
                    a[mi][1] = As[r + g + 8][kk + t4];
                    a[mi][2] = As[r + g][kk + t4 + 4];
                    a[mi][3] = As[r + g + 8][kk + t4 + 4];
                }
#pragma unroll
                for (int ni = 0; ni < 8; ni++) {
                    int n = wc + ni * 8 + g;
                    b[ni][0] = Ws[n][kk + t4];
                    b[ni][1] = Ws[n][kk + t4 + 4];
                }
#pragma unroll
                for (int mi = 0; mi < 2; mi++)
#pragma unroll
                    for (int ni = 0; ni < 8; ni++)
                        mma_tf32(acc[mi][ni], a[mi], b[ni]);
            }
        }
    }
    // epilogue: add bias, write
#pragma unroll
    for (int mi = 0; mi < 2; mi++) {
        int r1 = r0 + wr + mi * 16 + g;
        int r2 = r1 + 8;
#pragma unroll
        for (int ni = 0; ni < 8; ni++) {
            int cc = wc + ni * 8 + 2 * t4;
            float b0 = bias[cc], b1 = bias[cc + 1];
            if (r1 < NN) {
                Cp[(size_t)r1 * ldc + cbase + cc] = acc[mi][ni][0] + b0;
                Cp[(size_t)r1 * ldc + cbase + cc + 1] = acc[mi][ni][1] + b1;
            }
            if (r2 < NN) {
                Cp[(size_t)r2 * ldc + cbase + cc] = acc[mi][ni][2] + b0;
                Cp[(size_t)r2 * ldc + cbase + cc + 1] = acc[mi][ni][3] + b1;
            }
        }
    }
}

// X = neigh @ w_rel^T + x @ w_root^T + b_rel
__global__ void __launch_bounds__(256, 1) gemm_x_k(
    const float* __restrict__ A0, const float* __restrict__ A1,
    const float* __restrict__ W0, const float* __restrict__ W1,
    const float* __restrict__ bias, float* __restrict__ Cp) {
    __shared__ unsigned As[128][36];
    __shared__ unsigned Ws[128][36];
    const float* Ap[3] = {A0, A1, nullptr};
    const float* Wp[3] = {W0, W1, nullptr};
    const float* Zn[3] = {nullptr, nullptr, nullptr};
    gemm_core(Ap, Wp, Zn, Zn, 2, 128, bias, Cp, 128, blockIdx.x * 128, 0, As, Ws);
}

// Hm strips: strip j uses inputs [BN(X),H1,H2][0..j], W block row j
__global__ void __launch_bounds__(256, 1) gemm_hm_k(
    const float* __restrict__ lin_w, const float* __restrict__ lin_b) {
    __shared__ unsigned As[128][36];
    __shared__ unsigned Ws[128][36];
    int j = blockIdx.y;
    const float* Ap[3] = {d_X, d_H1, d_H2};
    const float* Wp[3];
    for (int i = 0; i < 3; i++)
        Wp[i] = lin_w + (size_t)(j * 128) * M3 + i * 128;
    const float* Sc[3] = {d_scX, nullptr, nullptr};
    const float* Sh[3] = {d_shX, nullptr, nullptr};
    gemm_core(Ap, Wp, Sc, Sh, j + 1, M3, lin_b + j * 128, d_Hm, M3,
              blockIdx.x * 128, j * 128, As, Ws);
}

// ---------------- per-column sum/sumsq over NN rows (vectorized) ----------------
__global__ void stats2_k(const float* __restrict__ A, int ncol, float* __restrict__ st,
                         int rows_per_blk) {
    __shared__ float sm[384 * 8];
    int n4 = ncol >> 2;
    int c4 = threadIdx.x % n4;
    int rl = threadIdx.x / n4;
    int rstep = blockDim.x / n4;
    int r0 = blockIdx.x * rows_per_blk;
    int rend = min(r0 + rows_per_blk, NN);
    float4 s = make_float4(0, 0, 0, 0), q = make_float4(0, 0, 0, 0);
    for (int r = r0 + rl; r < rend; r += rstep) {
        float4 v = __ldg((const float4*)(A + (size_t)r * ncol) + c4);
        s.x += v.x; s.y += v.y; s.z += v.z; s.w += v.w;
        q.x += v.x * v.x; q.y += v.y * v.y; q.z += v.z * v.z; q.w += v.w * v.w;
    }
    float* my = sm + threadIdx.x * 8;
    my[0] = s.x; my[1] = s.y; my[2] = s.z; my[3] = s.w;
    my[4] = q.x; my[5] = q.y; my[6] = q.z; my[7] = q.w;
    __syncthreads();
    if (threadIdx.x < (unsigned)n4) {
        float acc[8];
#pragma unroll
        for (int k = 0; k < 8; k++) acc[k] = 0.f;
        for (int j = 0; j < rstep; j++) {
            float* p = sm + (c4 + j * n4) * 8;
#pragma unroll
            for (int k = 0; k < 8; k++) acc[k] += p[k];
        }
#pragma unroll
        for (int k = 0; k < 4; k++) {
            atomicAdd(st + c4 * 4 + k, acc[k]);
            atomicAdd(st + ncol + c4 * 4 + k, acc[4 + k]);
        }
    }
}

// ---------------- finalize BN(X): stats -> per-channel scale/shift ----------------
__global__ void finalize_bnX_k(const float* __restrict__ gw, const float* __restrict__ gb) {
    int c = threadIdx.x;  // 128
    float mean = d_stX[c] * (1.f / NN);
    float var = d_stX[CDIM + c] * (1.f / NN) - mean * mean;
    float sc = gw[c] * rsqrtf(var + EPSB);
    d_scX[c] = sc;
    d_shX[c] = gb[c] - mean * sc;
}

// ---------------- pooling (fuses bnh BatchNorm apply) ----------------
__global__ void pool_k(const int* __restrict__ batch,
                       const float* __restrict__ gw, const float* __restrict__ gb) {
    int g = blockIdx.x;
    int c = threadIdx.x;  // 384
    int lo = 0, hi = NN;
    while (lo < hi) { int mid = (lo + hi) >> 1; if (batch[mid] < g) lo = mid + 1; else hi = mid; }
    int start = lo;
    lo = start; hi = NN;
    while (lo < hi) { int mid = (lo + hi) >> 1; if (batch[mid] < g + 1) lo = mid + 1; else hi = mid; }
    int end = lo;

    float mean = d_stH[c] * (1.f / NN);
    float var = d_stH[M3 + c] * (1.f / NN) - mean * mean;
    float sc = gw[c] * rsqrtf(var + EPSB);
    float sh = gb[c] - mean * sc;

    float s = 0.f;
    float mx = -INFINITY;
    for (int r = start; r < end; ++r) {
        float v = fmaf(d_Hm[(size_t)r * M3 + c], sc, sh);
        s += v;
        mx = fmaxf(mx, v);
    }
    int cnt = end - start;
    d_Hcat[(size_t)g * CAT + c] = (cnt > 0) ? s / (float)cnt : 0.f;
    d_Hcat[(size_t)g * CAT + 384 + c] = s;
    d_Hcat[(size_t)g * CAT + 768 + c] = (cnt > 0) ? mx : 0.f;
}

// ---------------- BN over graphs (128 rows x 1152 cols) ----------------
__global__ void bn_graphs_k(const float* __restrict__ gw, const float* __restrict__ gb) {
    int c = blockIdx.x * blockDim.x + threadIdx.x;
    if (c >= CAT) return;
    float s = 0.f, ss = 0.f;
    for (int r = 0; r < NG; r++) { float v = d_Hcat[r * CAT + c]; s += v; ss += v * v; }
    float mean = s * (1.f / NG);
    float var = ss * (1.f / NG) - mean * mean;
    float sc = gw[c] * rsqrtf(var + EPSB);
    float sh = gb[c] - mean * sc;
    for (int r = 0; r < NG; r++) d_Hbn[r * CAT + c] = fmaf(d_Hcat[r * CAT + c], sc, sh);
}

// ---------------- small dense layer ----------------
__global__ void mlp_k(const float* __restrict__ A, int Kd,
                      const float* __restrict__ W, const float* __restrict__ bias,
                      float* __restrict__ out, int Od, int do_relu) {
    extern __shared__ float sA[];  // 8*Kd
    int g0 = blockIdx.y * 8;
    for (int idx = threadIdx.x; idx < 8 * Kd; idx += blockDim.x)
        sA[idx] = A[(size_t)(g0 + idx / Kd) * Kd + (idx % Kd)];
    __syncthreads();
    int o = blockIdx.x * blockDim.x + threadIdx.x;
    float bb = bias[o];
    float acc[8];
#pragma unroll
    for (int j = 0; j < 8; j++) acc[j] = bb;
    const float* wr = W + (size_t)o * Kd;
    for (int k = 0; k < Kd; k++) {
        float w = wr[k];
#pragma unroll
        for (int j = 0; j < 8; j++) acc[j] = fmaf(w, sA[j * Kd + k], acc[j]);
    }
#pragma unroll
    for (int j = 0; j < 8; j++) {
        float v = acc[j];
        if (do_relu) v = fmaxf(v, 0.f);
        out[(size_t)(g0 + j) * Od + o] = v;
    }
}

// ---------------- final layer + log_softmax ----------------
__global__ void final_k(const float* __restrict__ w3, const float* __restrict__ b3,
                        float* __restrict__ out) {
    int g = threadIdx.x;
    if (g >= NG) return;
    float l0 = b3[0], l1 = b3[1];
    const float* h = d_h2 + (size_t)g * 384;
    for (int k = 0; k < 384; k++) {
        float v = h[k];
        l0 = fmaf(v, w3[k], l0);
        l1 = fmaf(v, w3[384 + k], l1);
    }
    float m = fmaxf(l0, l1);
    float lse = m + logf(expf(l0 - m) + expf(l1 - m));
    out[g * 2 + 0] = l0 - lse;
    out[g * 2 + 1] = l1 - lse;
}

extern "C" void kernel_launch(void* const* d_in, const int* in_sizes, int n_in,
                              void* d_out, int out_size) {
    const float* x      = (const float*)d_in[0];
    const int*   ei     = (const int*)d_in[1];
    const int*   batch  = (const int*)d_in[2];
    const float* w_rel  = (const float*)d_in[4];
    const float* b_rel  = (const float*)d_in[5];
    const float* w_root = (const float*)d_in[6];
    const float* n0g    = (const float*)d_in[7];
    const float* n0b    = (const float*)d_in[8];
    const float* lin_w  = (const float*)d_in[9];
    const float* lin_b  = (const float*)d_in[10];
    const float* bnh_g  = (const float*)d_in[11];
    const float* bnh_b  = (const float*)d_in[12];
    const float* bno_g  = (const float*)d_in[13];
    const float* bno_b  = (const float*)d_in[14];
    const float* w1     = (const float*)d_in[15];
    const float* b1     = (const float*)d_in[16];
    const float* w2     = (const float*)d_in[17];
    const float* b2     = (const float*)d_in[18];
    const float* w3     = (const float*)d_in[19];
    const float* b3     = (const float*)d_in[20];
    float* out = (float*)d_out;
    const int* row = ei;            // edge_index[0]
    const int* col = ei + NE;       // edge_index[1]

    float *p_neigh, *p_X, *p_H1, *p_H2, *p_Hm, *p_stX, *p_stH, *p_scX, *p_shX;
    float *p_Hbn, *p_h1, *p_h2;
    cudaGetSymbolAddress((void**)&p_neigh, d_neigh);
    cudaGetSymbolAddress((void**)&p_X, d_X);
    cudaGetSymbolAddress((void**)&p_H1, d_H1);
    cudaGetSymbolAddress((void**)&p_H2, d_H2);
    cudaGetSymbolAddress((void**)&p_Hm, d_Hm);
    cudaGetSymbolAddress((void**)&p_stX, d_stX);
    cudaGetSymbolAddress((void**)&p_stH, d_stH);
    cudaGetSymbolAddress((void**)&p_scX, d_scX);
    cudaGetSymbolAddress((void**)&p_shX, d_shX);
    cudaGetSymbolAddress((void**)&p_Hbn, d_Hbn);
    cudaGetSymbolAddress((void**)&p_h1, d_h1);
    cudaGetSymbolAddress((void**)&p_h2, d_h2);

    const int ROWBLK = (NN + 127) / 128;  // 391

    zero_all_k<<<(NN * CDIM) / 256, 256>>>();
    // neigh[col] += x[row]
    scatter_add_k<<<(NE * 32) / 256, 256>>>(x, p_neigh, row, col, nullptr, nullptr);
    // X = neigh @ w_rel^T + x @ w_root^T + b_rel   (tf32 tensor cores)
    gemm_x_k<<<ROWBLK, 256>>>(p_neigh, x, w_rel, w_root, b_rel, p_X);
    // BN(X) stats (standalone, high-parallelism) -> scale/shift
    stats2_k<<<400, 256>>>(p_X, 128, p_stX, 125);
    finalize_bnX_k<<<1, 128>>>(n0g, n0b);
    // H1[row] += BN(X)[col]  (affine fused into gather), H2[row] += H1[col]
    scatter_add_k<<<(NE * 32) / 256, 256>>>(p_X, p_H1, col, row, p_scX, p_shX);
    scatter_add_k<<<(NE * 32) / 256, 256>>>(p_H1, p_H2, col, row, nullptr, nullptr);
    // masked block-lower-triangular lin GEMM, 3 strips, BN(X) fused on input 0
    gemm_hm_k<<<dim3(ROWBLK, 3), 256>>>(lin_w, lin_b);
    stats2_k<<<400, 384>>>(p_Hm, 384, p_stH, 125);
    pool_k<<<NG, 384>>>(batch, bnh_g, bnh_b);
    bn_graphs_k<<<CAT / 128, 128>>>(bno_g, bno_b);
    mlp_k<<<dim3(768 / 128, NG / 8), 128, 8 * 1152 * sizeof(float)>>>(
        p_Hbn, 1152, w1, b1, p_h1, 768, 1);
    mlp_k<<<dim3(384 / 128, NG / 8), 128, 8 * 768 * sizeof(float)>>>(
        p_h1, 768, w2, b2, p_h2, 384, 1);
    final_k<<<1, 128>>>(w3, b3, out);
}